// round 14
// baseline (speedup 1.0000x reference)
#include <cuda_runtime.h>
#include <math.h>
#include <stdint.h>

// ---------------- problem constants ----------------
#define B_    16
#define C_    64
#define HW    441
#define NCLS  10
#define M_    2205
#define MT    128            // m tile
#define NT    18             // m tiles (18*128 = 2304)
#define MP    2304
#define ROWS  7056
#define RT    128            // row tile
#define RB    56             // row blocks (56*128 = 7168)
#define ROWSP 7168
#define NQU   7168           // q rows (padded)
#define NSU   23040          // s rows (10*2304)
#define NU    (NQU + NSU)    // 30208 -> 944 blocks of 32 rows
#define TILEB 8192           // bytes per 128-row int8 swizzled tile (64B rows)

// Fixed quantization: x_int8 = round(clamp(x,±0.75) * 127/0.75)
#define QSCALE (127.0f / 0.75f)
#define SCALEF (0.5625f / 16129.0f)   // (0.75/127)^2 : int-sim -> cosine

// ---------------- device scratch (no allocation allowed) ----------------
// int8 descriptors stored PRE-SWIZZLED per 8KB tile: 128 rows x 64B, packed
// two rows per 128B line (row r -> line r>>1, half r&1), SW128 on the line.
__device__ __align__(16) unsigned char g_q8[RB * TILEB];
__device__ __align__(16) unsigned char g_s8[NCLS * NT * TILEB];
__device__ float g_part[NCLS * RB * 2];            // per-(n,block) b-segment sums

typedef uint32_t u32;

// ---------------- PTX helpers (all plain-sm_103-safe) ----------------
__device__ __forceinline__ u32 smem_u32(const void* p){
    u32 a;
    asm("{ .reg .u64 t; cvta.to.shared.u64 t, %1; cvt.u32.u64 %0, t; }" : "=r"(a) : "l"(p));
    return a;
}
__device__ __forceinline__ int imax(int a, int b){ return a > b ? a : b; }
__device__ __forceinline__ int imin(int a, int b){ return a < b ? a : b; }
// Scalar branchless sorted top-3 insert (s32).
__device__ __forceinline__ void ins3i(int v, int& a, int& b, int& c){
    int na = imax(a, v);
    int nb = imax(b, imin(a, v));
    int nc = imax(c, imin(b, v));
    a = na; b = nb; c = nc;
}
// Packed s16x2 min/max (PTX 8.0, sm_90+ generic).
__device__ __forceinline__ u32 vmax2(u32 a, u32 b){
    u32 d; asm("max.s16x2 %0, %1, %2;" : "=r"(d) : "r"(a), "r"(b)); return d;
}
__device__ __forceinline__ u32 vmin2(u32 a, u32 b){
    u32 d; asm("min.s16x2 %0, %1, %2;" : "=r"(d) : "r"(a), "r"(b)); return d;
}
// Packed s16x2 top-3 insert: two independent streams per register.
__device__ __forceinline__ void ins3p(u32 v, u32& a, u32& b, u32& c){
    u32 na = vmax2(a, v);
    u32 nb = vmax2(b, vmin2(a, v));
    u32 nc = vmax2(c, vmin2(b, v));
    a = na; b = nb; c = nc;
}
// Pack two s32 sims into s16x2 (saturating; |sim| <= ~28.7K so exact).
#define PACKS16(d, hi, lo) \
    asm("cvt.pack.sat.s16.s32 %0, %1, %2;" : "=r"(d) : "r"(hi), "r"(lo))

#define SW(off) ((u32)(off) ^ (((u32)(off) >> 3) & 0x70u))
// swizzled byte offset of (row, chunk-byte cb) in an 8KB tile
__device__ __forceinline__ u32 swa(int row, int cb){
    u32 off = (u32)((row >> 1) * 128 + (row & 1) * 64 + cb);
    return off ^ ((off >> 3) & 0x70u);
}

#define MBAR_INIT(mbar, cnt) \
    asm volatile("mbarrier.init.shared.b64 [%0], %1;" :: "r"(mbar), "r"(cnt) : "memory")
#define EXPECT_TX(mbar, nb) \
    asm volatile("mbarrier.arrive.expect_tx.shared.b64 _, [%0], %1;" :: "r"(mbar), "r"(nb) : "memory")
#define BULK_G2S(dst, src, nb, mbar) \
    asm volatile("cp.async.bulk.shared::cluster.global.mbarrier::complete_tx::bytes " \
                 "[%0], [%1], %2, [%3];" \
                 :: "r"(dst), "l"(src), "r"(nb), "r"(mbar) : "memory")

__device__ __forceinline__ void mbar_wait(u32 mbar, u32 parity){
    asm volatile(
        "{\n\t.reg .pred P;\n"
        "LW_%=:\n\t"
        "mbarrier.try_wait.parity.acquire.cta.shared::cta.b64 P, [%0], %1, 0x989680;\n\t"
        "@P bra LD_%=;\n\t"
        "bra LW_%=;\n"
        "LD_%=:\n\t}"
        :: "r"(mbar), "r"(parity) : "memory");
}

#define LDMX4(r, a) \
    asm volatile("ldmatrix.sync.aligned.m8n8.x4.shared.b16 {%0,%1,%2,%3}, [%4];" \
        : "=r"((r)[0]), "=r"((r)[1]), "=r"((r)[2]), "=r"((r)[3]) : "r"(a))

#define MMAS8(c, a, b0, b1) \
    asm volatile("mma.sync.aligned.m16n8k32.row.col.s32.s8.s8.s32 " \
        "{%0,%1,%2,%3}, {%4,%5,%6,%7}, {%8,%9}, {%0,%1,%2,%3};" \
        : "+r"((c)[0]), "+r"((c)[1]), "+r"((c)[2]), "+r"((c)[3]) \
        : "r"((a)[0]), "r"((a)[1]), "r"((a)[2]), "r"((a)[3]), "r"(b0), "r"(b1))

// smem: [0,8) mbarA, [8,16) mb0, [16,24) mb1,
// [1024,9216) A tile (reused as merge buf), [9216,17408) B0, [17408,25600) B1.
#define OFF_MBA  0u
#define OFF_MB0  8u
#define OFF_MB1  16u
#define OFF_A    1024u
#define OFF_B0   9216u
#define OFF_B1   17408u
#define SMEM_REQ 25600

// ---------------------------------------------------------------------------
// Normalize + int8-quantize, 8 threads per descriptor row. Output pre-swizzled
// per 8KB tile; each thread writes one 8B chunk (inside one 16B swizzle unit).
// ---------------------------------------------------------------------------
__global__ void norm_kernel(const float* __restrict__ x1, const float* __restrict__ x2){
    const int u   = blockIdx.x * 32 + (threadIdx.x >> 3);
    const int sub = threadIdx.x & 7;             // c-chunk: c = sub*8 .. sub*8+7

    float v[8];
    unsigned char* outp;
    if (u < NQU){
        const int blk = u >> 7, r = u & 127;
        outp = g_q8 + (size_t)blk * TILEB + SW(r * 64 + (r & 1) * 0 + 0);  // placeholder
        outp = g_q8 + (size_t)blk * TILEB + swa(r, sub * 8);
        if (u >= ROWS){
            #pragma unroll
            for (int j = 0; j < 8; j++) v[j] = 0.f;
        } else {
            int b  = u / HW;
            int qi = u - b * HW;
            const float* p = x1 + (size_t)b * C_ * HW + qi + (size_t)(sub * 8) * HW;
            #pragma unroll
            for (int j = 0; j < 8; j++) v[j] = p[j * HW];
        }
    } else {
        int w = u - NQU;
        int n = w / MP;
        int m = w - n * MP;
        const int t = m >> 7, r = m & 127;
        outp = g_s8 + (size_t)(n * NT + t) * TILEB + swa(r, sub * 8);
        if (m >= M_){
            #pragma unroll
            for (int j = 0; j < 8; j++) v[j] = 0.f;
        } else {
            const float* p = x2 + (size_t)n * C_ * M_ + m + (size_t)(sub * 8) * M_;
            #pragma unroll
            for (int j = 0; j < 8; j++) v[j] = p[j * M_];
        }
    }
    float ss = 0.f;
    #pragma unroll
    for (int j = 0; j < 8; j++) ss += v[j] * v[j];
    #pragma unroll
    for (int o = 1; o <= 4; o <<= 1) ss += __shfl_xor_sync(0xffffffffu, ss, o);
    float qs = (1.f / fmaxf(sqrtf(ss), 1e-12f)) * QSCALE;

    int q[8];
    #pragma unroll
    for (int j = 0; j < 8; j++){
        float f = fminf(fmaxf(v[j] * qs, -127.f), 127.f);
        q[j] = __float2int_rn(f);
    }
    uint2 o2;
    o2.x = (u32)(q[0] & 255) | ((u32)(q[1] & 255) << 8)
         | ((u32)(q[2] & 255) << 16) | ((u32)q[3] << 24);
    o2.y = (u32)(q[4] & 255) | ((u32)(q[5] & 255) << 8)
         | ((u32)(q[6] & 255) << 16) | ((u32)q[7] << 24);
    *reinterpret_cast<uint2*>(outp) = o2;
}

// ---------------------------------------------------------------------------
// Main: int8 mma.sync GEMM (CTA 128x128, K=64, m16n8k32) + fused packed-s16
// top-3 on raw s32 sims (uniform per-(row,class) scale preserves order; the
// cosine bound |acc| <= 28.7K < 32767 makes cvt.pack.sat.s16 exact).
// ---------------------------------------------------------------------------
__global__ void __launch_bounds__(256, 2) sim_mma_kernel(){
    extern __shared__ __align__(16) char smem[];
    const u32 sb   = smem_u32(smem);
    const int tid  = threadIdx.x;
    const int wid  = tid >> 5;
    const int lane = tid & 31;
    const int n    = blockIdx.y;
    const int blk  = blockIdx.x;
    const int row0 = blk * RT;
    const int mrow = (wid & 3) * 32;          // warp's row offset in tile
    const int ncol = (wid >> 2) * 64;         // warp's col offset in tile

    const unsigned char* gA = g_q8 + (size_t)blk * TILEB;
    const unsigned char* gB = g_s8 + (size_t)n * NT * TILEB;

    if (tid == 0){
        MBAR_INIT(sb + OFF_MBA, 1);
        MBAR_INIT(sb + OFF_MB0, 1);
        MBAR_INIT(sb + OFF_MB1, 1);
    }
    __syncthreads();
    if (tid == 0){
        EXPECT_TX(sb + OFF_MBA, TILEB); BULK_G2S(sb + OFF_A,  gA,         TILEB, sb + OFF_MBA);
        EXPECT_TX(sb + OFF_MB0, TILEB); BULK_G2S(sb + OFF_B0, gB,         TILEB, sb + OFF_MB0);
        EXPECT_TX(sb + OFF_MB1, TILEB); BULK_G2S(sb + OFF_B1, gB + TILEB, TILEB, sb + OFF_MB1);
    }

    const int rA   = lane & 15;               // ldmatrix row-within-frag
    const int kh16 = (lane >> 4) * 16;        // ldmatrix 16B k-chunk select

    // A is tile-loop invariant: hoist fragments (2 k-steps x 8 regs).
    mbar_wait(sb + OFF_MBA, 0);
    u32 af[2][8];
    #pragma unroll
    for (int ks = 0; ks < 2; ks++){
        const u32 aaddr = sb + OFF_A + swa(mrow + rA, ks * 32 + kh16);
        LDMX4(af[ks],     aaddr);             // rows mrow..mrow+15
        LDMX4(af[ks] + 4, aaddr + 1024u);     // rows mrow+16..mrow+31 (+8 lines)
    }

    // Packed top-3 state: slot s = mf*2 + half; two col-streams per slot.
    u32 P0[4], P1[4], P2[4];
    #pragma unroll
    for (int s = 0; s < 4; s++){ P0[s] = 0x80008000u; P1[s] = 0x80008000u; P2[s] = 0x80008000u; }

    u32 phase[2] = {0u, 0u};

    for (int t = 0; t < NT; t++){
        const int buf = t & 1;
        const u32 mb  = sb + (buf ? OFF_MB1 : OFF_MB0);
        mbar_wait(mb, phase[buf]);
        phase[buf] ^= 1u;
        const u32 bbase = sb + (buf ? OFF_B1 : OFF_B0);

        #pragma unroll
        for (int pass = 0; pass < 2; pass++){
            int c[2][4][4];
            #pragma unroll
            for (int mf = 0; mf < 2; mf++)
                #pragma unroll
                for (int nf = 0; nf < 4; nf++)
                    #pragma unroll
                    for (int q = 0; q < 4; q++) c[mf][nf][q] = 0;

            #pragma unroll
            for (int ks = 0; ks < 2; ks++){
                u32 bf[8];
                const u32 baddr = bbase + swa(ncol + pass * 32 + rA, ks * 32 + kh16);
                LDMX4(bf,     baddr);           // n rows base..base+15
                LDMX4(bf + 4, baddr + 1024u);   // n rows +16..+31
                MMAS8(c[0][0], af[ks],     bf[0], bf[2]);
                MMAS8(c[0][1], af[ks],     bf[1], bf[3]);
                MMAS8(c[0][2], af[ks],     bf[4], bf[6]);
                MMAS8(c[0][3], af[ks],     bf[5], bf[7]);
                MMAS8(c[1][0], af[ks] + 4, bf[0], bf[2]);
                MMAS8(c[1][1], af[ks] + 4, bf[1], bf[3]);
                MMAS8(c[1][2], af[ks] + 4, bf[4], bf[6]);
                MMAS8(c[1][3], af[ks] + 4, bf[5], bf[7]);
            }

            // Fold raw s32 sims into packed s16x2 running top-3.
            if (t < NT - 1){
                #pragma unroll
                for (int mf = 0; mf < 2; mf++)
                    #pragma unroll
                    for (int nf = 0; nf < 4; nf++){
                        u32 k0, k1;
                        PACKS16(k0, c[mf][nf][1], c[mf][nf][0]);
                        PACKS16(k1, c[mf][nf][3], c[mf][nf][2]);
                        ins3p(k0, P0[mf*2],   P1[mf*2],   P2[mf*2]);
                        ins3p(k1, P0[mf*2+1], P1[mf*2+1], P2[mf*2+1]);
                    }
            } else {
                const int rem = M_ - (NT - 1) * MT;   // 29 valid cols in last tile
                #pragma unroll
                for (int nf = 0; nf < 4; nf++){
                    const int col0 = ncol + pass * 32 + nf * 8 + (lane & 3) * 2;
                    const bool v0 = col0     < rem;
                    const bool v1 = col0 + 1 < rem;
                    #pragma unroll
                    for (int mf = 0; mf < 2; mf++){
                        int e0 = v0 ? c[mf][nf][0] : INT_MIN;
                        int e1 = v1 ? c[mf][nf][1] : INT_MIN;
                        int e2 = v0 ? c[mf][nf][2] : INT_MIN;
                        int e3 = v1 ? c[mf][nf][3] : INT_MIN;
                        u32 k0, k1;
                        PACKS16(k0, e1, e0);
                        PACKS16(k1, e3, e2);
                        ins3p(k0, P0[mf*2],   P1[mf*2],   P2[mf*2]);
                        ins3p(k1, P0[mf*2+1], P1[mf*2+1], P2[mf*2+1]);
                    }
                }
            }
        }
        // All smem reads of this buffer done; refill with one bulk copy.
        __syncthreads();
        if (t + 2 < NT && tid == 0){
            const u32 dst = sb + (buf ? OFF_B1 : OFF_B0);
            EXPECT_TX(mb, TILEB);
            BULK_G2S(dst, gB + (size_t)(t + 2) * TILEB, TILEB, mb);
        }
    }

    // Collapse packed streams -> scalar s32 top-3 per slot.
    int t0[4], t1[4], t2[4];
    #pragma unroll
    for (int s = 0; s < 4; s++){
        t0[s] = INT_MIN; t1[s] = INT_MIN; t2[s] = INT_MIN;
        #pragma unroll
        for (int w = 0; w < 3; w++){
            u32 p = (w == 0) ? P0[s] : (w == 1) ? P1[s] : P2[s];
            int lo = ((int)(p << 16)) >> 16;
            int hi = ((int)p) >> 16;
            ins3i(lo, t0[s], t1[s], t2[s]);
            ins3i(hi, t0[s], t1[s], t2[s]);
        }
    }
    // Merge across the 4 lanes sharing each row.
    #pragma unroll
    for (int off = 1; off <= 2; off <<= 1){
        #pragma unroll
        for (int s = 0; s < 4; s++){
            int u0 = __shfl_xor_sync(0xffffffffu, t0[s], off);
            int u1 = __shfl_xor_sync(0xffffffffu, t1[s], off);
            int u2 = __shfl_xor_sync(0xffffffffu, t2[s], off);
            ins3i(u0, t0[s], t1[s], t2[s]);
            ins3i(u1, t0[s], t1[s], t2[s]);
            ins3i(u2, t0[s], t1[s], t2[s]);
        }
    }
    // Merge the two column-half warps via smem (A region is dead now).
    int*   mrg  = reinterpret_cast<int*>(smem + OFF_A);          // 384 ints
    float* rsum = reinterpret_cast<float*>(smem + OFF_A + 2048); // 128 floats
    __syncthreads();
    if (wid >= 4 && (lane & 3) == 0){
        #pragma unroll
        for (int s = 0; s < 4; s++){
            int row = mrow + (s >> 1) * 16 + (s & 1) * 8 + (lane >> 2);
            mrg[row * 3 + 0] = t0[s];
            mrg[row * 3 + 1] = t1[s];
            mrg[row * 3 + 2] = t2[s];
        }
    }
    __syncthreads();
    if (wid < 4 && (lane & 3) == 0){
        #pragma unroll
        for (int s = 0; s < 4; s++){
            int row = mrow + (s >> 1) * 16 + (s & 1) * 8 + (lane >> 2);
            ins3i(mrg[row * 3 + 0], t0[s], t1[s], t2[s]);
            ins3i(mrg[row * 3 + 1], t0[s], t1[s], t2[s]);
            ins3i(mrg[row * 3 + 2], t0[s], t1[s], t2[s]);
            rsum[row] = (float)(t0[s] + t1[s] + t2[s]) * SCALEF;
        }
    }
    __syncthreads();
    // Block reduction split by batch-image boundary (<=1 boundary: 441 > 128).
    if (wid == 0){
        const int b0    = row0 / HW;
        const int split = (b0 + 1) * HW - row0;   // may be >= 128 (no boundary)
        float lo = 0.f, hi = 0.f;
        #pragma unroll
        for (int i = 0; i < 4; i++){
            int r = lane + 32 * i;
            float v = rsum[r];
            if (r < split) lo += v; else hi += v;
        }
        #pragma unroll
        for (int o = 16; o; o >>= 1){
            lo += __shfl_down_sync(0xffffffffu, lo, o);
            hi += __shfl_down_sync(0xffffffffu, hi, o);
        }
        if (lane == 0){
            g_part[(n * RB + blk) * 2 + 0] = lo;
            g_part[(n * RB + blk) * 2 + 1] = hi;   // belongs to b0+1 (dropped if 16)
        }
    }
}

// ---------------------------------------------------------------------------
// out[b][n] = sum of partials mapping to b. One block.
// ---------------------------------------------------------------------------
__global__ void reduce_out_kernel(float* __restrict__ out){
    const int tid = threadIdx.x;
    if (tid >= B_ * NCLS) return;
    const int b = tid / NCLS;
    const int n = tid % NCLS;
    float s = 0.f;
    #pragma unroll 8
    for (int blk = 0; blk < RB; blk++){
        int b0 = (blk * RT) / HW;
        float v0 = g_part[(n * RB + blk) * 2 + 0];
        float v1 = g_part[(n * RB + blk) * 2 + 1];
        if (b0 == b)     s += v0;
        if (b0 + 1 == b) s += v1;
    }
    out[tid] = s;
}

extern "C" void kernel_launch(void* const* d_in, const int* in_sizes, int n_in,
                              void* d_out, int out_size){
    const float* x1 = (const float*)d_in[0];   // [16,64,21,21] fp32
    const float* x2 = (const float*)d_in[1];   // [10,64,2205]  fp32
    float* out = (float*)d_out;                // [16,10] fp32

    cudaFuncSetAttribute(sim_mma_kernel,
                         cudaFuncAttributeMaxDynamicSharedMemorySize, SMEM_REQ);
    norm_kernel<<<NU / 32, 256>>>(x1, x2);
    sim_mma_kernel<<<dim3(RB, NCLS), 256, SMEM_REQ>>>();
    reduce_out_kernel<<<1, 192>>>(out);
}

// round 16
// speedup vs baseline: 2.2092x; 2.2092x over previous
#include <cuda_runtime.h>
#include <cuda_fp16.h>
#include <math.h>
#include <stdint.h>

// ---------------- problem constants ----------------
#define B_    16
#define C_    64
#define HW    441
#define NCLS  10
#define M_    2205
#define MT    128            // m tile
#define NT    18             // m tiles (18*128 = 2304)
#define MP    2304
#define ROWS  7056
#define RT    128            // row tile
#define RB    56             // row blocks (56*128 = 7168)
#define ROWSP 7168
#define NQU   7168           // q rows (padded)
#define NSU   23040          // s rows (10*2304)
#define NU    (NQU + NSU)    // 30208 -> 944 blocks of 32 rows
#define TILEB 16384          // bytes per 128-row fp16 swizzled tile (128B rows)

// ---------------- device scratch (no allocation allowed) ----------------
// fp16 descriptors stored PRE-SWIZZLED per 16KB tile so one contiguous
// cp.async.bulk reproduces the SW128 smem image ldmatrix expects.
__device__ __align__(16) __half g_qh[ROWSP * C_];
__device__ __align__(16) __half g_sh[NCLS * MP * C_];
__device__ float g_part[NCLS * RB * 2];            // per-(n,block) b-segment sums

typedef uint32_t u32;

// ---------------- PTX helpers (all plain-sm_103-safe) ----------------
__device__ __forceinline__ u32 smem_u32(const void* p){
    u32 a;
    asm("{ .reg .u64 t; cvta.to.shared.u64 t, %1; cvt.u32.u64 %0, t; }" : "=r"(a) : "l"(p));
    return a;
}
// Scalar branchless sorted top-3 insert.
__device__ __forceinline__ void ins3(float v, float& a, float& b, float& c){
    float na = fmaxf(a, v);
    float nb = fmaxf(b, fminf(a, v));
    float nc = fmaxf(c, fminf(b, v));
    a = na; b = nb; c = nc;
}
// Packed half2 top-3 insert: two independent streams per register.
__device__ __forceinline__ void ins3ph(__half2 v, __half2& a, __half2& b, __half2& c){
    __half2 na = __hmax2(a, v);
    __half2 nb = __hmax2(b, __hmin2(a, v));
    __half2 nc = __hmax2(c, __hmin2(b, v));
    a = na; b = nb; c = nc;
}

#define SW(off) ((u32)(off) ^ (((u32)(off) >> 3) & 0x70u))

#define MBAR_INIT(mbar, cnt) \
    asm volatile("mbarrier.init.shared.b64 [%0], %1;" :: "r"(mbar), "r"(cnt) : "memory")
#define EXPECT_TX(mbar, nb) \
    asm volatile("mbarrier.arrive.expect_tx.shared.b64 _, [%0], %1;" :: "r"(mbar), "r"(nb) : "memory")
#define BULK_G2S(dst, src, nb, mbar) \
    asm volatile("cp.async.bulk.shared::cluster.global.mbarrier::complete_tx::bytes " \
                 "[%0], [%1], %2, [%3];" \
                 :: "r"(dst), "l"(src), "r"(nb), "r"(mbar) : "memory")

__device__ __forceinline__ void mbar_wait(u32 mbar, u32 parity){
    asm volatile(
        "{\n\t.reg .pred P;\n"
        "LW_%=:\n\t"
        "mbarrier.try_wait.parity.acquire.cta.shared::cta.b64 P, [%0], %1, 0x989680;\n\t"
        "@P bra LD_%=;\n\t"
        "bra LW_%=;\n"
        "LD_%=:\n\t}"
        :: "r"(mbar), "r"(parity) : "memory");
}

#define LDMX4(r, a) \
    asm volatile("ldmatrix.sync.aligned.m8n8.x4.shared.b16 {%0,%1,%2,%3}, [%4];" \
        : "=r"((r)[0]), "=r"((r)[1]), "=r"((r)[2]), "=r"((r)[3]) : "r"(a))

// fp16 in, fp16 accumulate: c = 2 regs (4 halves).
// c[0] -> row = lane>>2,     cols 2*(lane&3)+{0,1}
// c[1] -> row = (lane>>2)+8, same cols
#define MMAF16(c, a, b0, b1) \
    asm volatile("mma.sync.aligned.m16n8k16.row.col.f16.f16.f16.f16 " \
        "{%0,%1}, {%2,%3,%4,%5}, {%6,%7}, {%0,%1};" \
        : "+r"((c)[0]), "+r"((c)[1]) \
        : "r"((a)[0]), "r"((a)[1]), "r"((a)[2]), "r"((a)[3]), "r"(b0), "r"(b1))

// smem: [0,8) mbarA, [8,16) mb0, [16,24) mb1,
// [1024,17408) A tile (reused as merge buf), [17408,33792) B0, [33792,50176) B1.
#define OFF_MBA  0u
#define OFF_MB0  8u
#define OFF_MB1  16u
#define OFF_A    1024u
#define OFF_B0   17408u
#define OFF_B1   33792u
#define SMEM_REQ 50176

// ---------------------------------------------------------------------------
// Normalize -> fp16, 8 threads per descriptor row; output pre-swizzled per
// 16KB tile (128B rows). Each thread writes one 16B chunk.
// ---------------------------------------------------------------------------
__global__ void norm_kernel(const float* __restrict__ x1, const float* __restrict__ x2){
    const int u   = blockIdx.x * 32 + (threadIdx.x >> 3);
    const int sub = threadIdx.x & 7;             // c-chunk: c = sub*8 .. sub*8+7

    float v[8];
    char* outp;
    if (u < NQU){
        const int blk = u >> 7, r = u & 127;
        outp = (char*)g_qh + (size_t)blk * TILEB + SW(r * 128 + sub * 16);
        if (u >= ROWS){
            #pragma unroll
            for (int j = 0; j < 8; j++) v[j] = 0.f;
        } else {
            int b  = u / HW;
            int qi = u - b * HW;
            const float* p = x1 + (size_t)b * C_ * HW + qi + (size_t)(sub * 8) * HW;
            #pragma unroll
            for (int j = 0; j < 8; j++) v[j] = p[j * HW];
        }
    } else {
        int w = u - NQU;
        int n = w / MP;
        int m = w - n * MP;
        const int t = m >> 7, r = m & 127;
        outp = (char*)g_sh + (size_t)(n * NT + t) * TILEB + SW(r * 128 + sub * 16);
        if (m >= M_){
            #pragma unroll
            for (int j = 0; j < 8; j++) v[j] = 0.f;
        } else {
            const float* p = x2 + (size_t)n * C_ * M_ + m + (size_t)(sub * 8) * M_;
            #pragma unroll
            for (int j = 0; j < 8; j++) v[j] = p[j * M_];
        }
    }
    float ss = 0.f;
    #pragma unroll
    for (int j = 0; j < 8; j++) ss += v[j] * v[j];
    #pragma unroll
    for (int o = 1; o <= 4; o <<= 1) ss += __shfl_xor_sync(0xffffffffu, ss, o);
    float inv = 1.f / fmaxf(sqrtf(ss), 1e-12f);

    __half2 o2[4];
    #pragma unroll
    for (int j = 0; j < 4; j++)
        o2[j] = __floats2half2_rn(v[2*j] * inv, v[2*j+1] * inv);
    *reinterpret_cast<uint4*>(outp) = *reinterpret_cast<uint4*>(o2);
}

// ---------------------------------------------------------------------------
// Main: fp16 mma.sync GEMM, fp16 ACCUMULATE (CTA 128x128, K=64) + fused
// packed-half2 top-3 directly on the accumulator registers (zero CVT).
// grid = (56, 10), block = 256 (8 warps). Warp tile 32 rows x 64 cols in two
// 32-col passes. cp.async.bulk double-buffered B tiles; A resident/hoisted.
// ---------------------------------------------------------------------------
__global__ void __launch_bounds__(256, 2) sim_mma_kernel(){
    extern __shared__ __align__(16) char smem[];
    const u32 sb   = smem_u32(smem);
    const int tid  = threadIdx.x;
    const int wid  = tid >> 5;
    const int lane = tid & 31;
    const int n    = blockIdx.y;
    const int blk  = blockIdx.x;
    const int row0 = blk * RT;
    const int mrow = (wid & 3) * 32;          // warp's row offset in tile
    const int ncol = (wid >> 2) * 64;         // warp's col offset in tile

    const char* gA = (const char*)g_qh + (size_t)blk * TILEB;
    const char* gB = (const char*)g_sh + (size_t)n * NT * TILEB;

    if (tid == 0){
        MBAR_INIT(sb + OFF_MBA, 1);
        MBAR_INIT(sb + OFF_MB0, 1);
        MBAR_INIT(sb + OFF_MB1, 1);
    }
    __syncthreads();
    if (tid == 0){
        EXPECT_TX(sb + OFF_MBA, TILEB); BULK_G2S(sb + OFF_A,  gA,         TILEB, sb + OFF_MBA);
        EXPECT_TX(sb + OFF_MB0, TILEB); BULK_G2S(sb + OFF_B0, gB,         TILEB, sb + OFF_MB0);
        EXPECT_TX(sb + OFF_MB1, TILEB); BULK_G2S(sb + OFF_B1, gB + TILEB, TILEB, sb + OFF_MB1);
    }

    const int rA    = lane & 15;              // ldmatrix row-within-frag
    const int khalf = (lane >> 4) * 8;        // ldmatrix k-half
    const u32 swx   = (u32)((rA & 7) << 4);   // SW128 xor term (row low bits)

    // A is tile-loop invariant: hoist all A fragments (32 regs).
    mbar_wait(sb + OFF_MBA, 0);
    u32 af[4][8];
    #pragma unroll
    for (int ks = 0; ks < 4; ks++){
        const u32 colb  = ((u32)((ks * 16 + khalf) * 2)) ^ swx;
        const u32 aaddr = sb + OFF_A + (u32)((mrow + rA) * 128) + colb;
        LDMX4(af[ks],     aaddr);
        LDMX4(af[ks] + 4, aaddr + 2048u);
    }

    // Packed top-3 state: slot s = mf*2 + half; two col-streams per slot.
    __half2 P0[4], P1[4], P2[4];
    {
        const u32 ninf = 0xFC00FC00u;          // half2(-inf,-inf)
        #pragma unroll
        for (int s = 0; s < 4; s++){
            P0[s] = *reinterpret_cast<const __half2*>(&ninf);
            P1[s] = *reinterpret_cast<const __half2*>(&ninf);
            P2[s] = *reinterpret_cast<const __half2*>(&ninf);
        }
    }

    u32 phase[2] = {0u, 0u};

    for (int t = 0; t < NT; t++){
        const int buf = t & 1;
        const u32 mb  = sb + (buf ? OFF_MB1 : OFF_MB0);
        mbar_wait(mb, phase[buf]);
        phase[buf] ^= 1u;
        const u32 bbase = sb + (buf ? OFF_B1 : OFF_B0) + (u32)((ncol + rA) * 128);

        #pragma unroll
        for (int pass = 0; pass < 2; pass++){
            u32 c[2][4][2];                    // half2 accumulators
            #pragma unroll
            for (int mf = 0; mf < 2; mf++)
                #pragma unroll
                for (int nf = 0; nf < 4; nf++){ c[mf][nf][0] = 0u; c[mf][nf][1] = 0u; }

            #pragma unroll
            for (int ks = 0; ks < 4; ks++){
                const u32 colb = ((u32)((ks * 16 + khalf) * 2)) ^ swx;
                u32 bA[4], bB[4];
                const u32 baddr = bbase + (u32)(pass * 32 * 128) + colb;
                LDMX4(bA, baddr);
                LDMX4(bB, baddr + 2048u);
                MMAF16(c[0][0], af[ks],     bA[0], bA[2]);
                MMAF16(c[0][1], af[ks],     bA[1], bA[3]);
                MMAF16(c[0][2], af[ks],     bB[0], bB[2]);
                MMAF16(c[0][3], af[ks],     bB[1], bB[3]);
                MMAF16(c[1][0], af[ks] + 4, bA[0], bA[2]);
                MMAF16(c[1][1], af[ks] + 4, bA[1], bA[3]);
                MMAF16(c[1][2], af[ks] + 4, bB[0], bB[2]);
                MMAF16(c[1][3], af[ks] + 4, bB[1], bB[3]);
            }

            // Fold accumulator half2s straight into the packed top-3.
            // c[mf][nf][r]: r=0 -> slot mf*2+0 (row lane>>2), r=1 -> slot mf*2+1.
            if (t < NT - 1){
                #pragma unroll
                for (int mf = 0; mf < 2; mf++)
                    #pragma unroll
                    for (int nf = 0; nf < 4; nf++){
                        ins3ph(*reinterpret_cast<__half2*>(&c[mf][nf][0]),
                               P0[mf*2],   P1[mf*2],   P2[mf*2]);
                        ins3ph(*reinterpret_cast<__half2*>(&c[mf][nf][1]),
                               P0[mf*2+1], P1[mf*2+1], P2[mf*2+1]);
                    }
            } else {
                const int rem = M_ - (NT - 1) * MT;   // 29 valid cols in last tile
                #pragma unroll
                for (int nf = 0; nf < 4; nf++){
                    const int col0 = ncol + pass * 32 + nf * 8 + (lane & 3) * 2;
                    const u32 limb = (col0 < rem ? 0x7C00u : 0xFC00u)
                                   | ((col0 + 1 < rem ? 0x7C00u : 0xFC00u) << 16);
                    const __half2 lim = *reinterpret_cast<const __half2*>(&limb);
                    #pragma unroll
                    for (int mf = 0; mf < 2; mf++){
                        ins3ph(__hmin2(*reinterpret_cast<__half2*>(&c[mf][nf][0]), lim),
                               P0[mf*2],   P1[mf*2],   P2[mf*2]);
                        ins3ph(__hmin2(*reinterpret_cast<__half2*>(&c[mf][nf][1]), lim),
                               P0[mf*2+1], P1[mf*2+1], P2[mf*2+1]);
                    }
                }
            }
        }
        // All smem reads of this buffer done; refill with one bulk copy.
        __syncthreads();
        if (t + 2 < NT && tid == 0){
            const u32 dst = sb + (buf ? OFF_B1 : OFF_B0);
            EXPECT_TX(mb, TILEB);
            BULK_G2S(dst, gB + (size_t)(t + 2) * TILEB, TILEB, mb);
        }
    }

    // Collapse packed streams -> scalar fp32 top-3 per slot.
    float s0[4], s1[4], s2[4];
    #pragma unroll
    for (int s = 0; s < 4; s++){
        s0[s] = -INFINITY; s1[s] = -INFINITY; s2[s] = -INFINITY;
        float2 a;
        a = __half22float2(P0[s]); ins3(a.x, s0[s], s1[s], s2[s]); ins3(a.y, s0[s], s1[s], s2[s]);
        a = __half22float2(P1[s]); ins3(a.x, s0[s], s1[s], s2[s]); ins3(a.y, s0[s], s1[s], s2[s]);
        a = __half22float2(P2[s]); ins3(a.x, s0[s], s1[s], s2[s]); ins3(a.y, s0[s], s1[s], s2[s]);
    }
    // Merge across the 4 lanes sharing each row.
    #pragma unroll
    for (int off = 1; off <= 2; off <<= 1){
        #pragma unroll
        for (int s = 0; s < 4; s++){
            float u0 = __shfl_xor_sync(0xffffffffu, s0[s], off);
            float u1 = __shfl_xor_sync(0xffffffffu, s1[s], off);
            float u2 = __shfl_xor_sync(0xffffffffu, s2[s], off);
            ins3(u0, s0[s], s1[s], s2[s]);
            ins3(u1, s0[s], s1[s], s2[s]);
            ins3(u2, s0[s], s1[s], s2[s]);
        }
    }
    // Merge the two column-half warps via smem (A region is dead now).
    float* mrg  = reinterpret_cast<float*>(smem + OFF_A);          // 384 floats
    float* rsum = reinterpret_cast<float*>(smem + OFF_A + 2048);   // 128 floats
    __syncthreads();
    if (wid >= 4 && (lane & 3) == 0){
        #pragma unroll
        for (int s = 0; s < 4; s++){
            int row = mrow + (s >> 1) * 16 + (s & 1) * 8 + (lane >> 2);
            mrg[row * 3 + 0] = s0[s];
            mrg[row * 3 + 1] = s1[s];
            mrg[row * 3 + 2] = s2[s];
        }
    }
    __syncthreads();
    if (wid < 4 && (lane & 3) == 0){
        #pragma unroll
        for (int s = 0; s < 4; s++){
            int row = mrow + (s >> 1) * 16 + (s & 1) * 8 + (lane >> 2);
            ins3(mrg[row * 3 + 0], s0[s], s1[s], s2[s]);
            ins3(mrg[row * 3 + 1], s0[s], s1[s], s2[s]);
            ins3(mrg[row * 3 + 2], s0[s], s1[s], s2[s]);
            rsum[row] = s0[s] + s1[s] + s2[s];   // padded rows naturally give 0
        }
    }
    __syncthreads();
    // Block reduction split by batch-image boundary (<=1 boundary: 441 > 128).
    if (wid == 0){
        const int b0    = row0 / HW;
        const int split = (b0 + 1) * HW - row0;   // may be >= 128 (no boundary)
        float lo = 0.f, hi = 0.f;
        #pragma unroll
        for (int i = 0; i < 4; i++){
            int r = lane + 32 * i;
            float v = rsum[r];
            if (r < split) lo += v; else hi += v;
        }
        #pragma unroll
        for (int o = 16; o; o >>= 1){
            lo += __shfl_down_sync(0xffffffffu, lo, o);
            hi += __shfl_down_sync(0xffffffffu, hi, o);
        }
        if (lane == 0){
            g_part[(n * RB + blk) * 2 + 0] = lo;
            g_part[(n * RB + blk) * 2 + 1] = hi;   // belongs to b0+1 (dropped if 16)
        }
    }
}

// ---------------------------------------------------------------------------
// out[b][n] = sum of partials mapping to b. One block.
// ---------------------------------------------------------------------------
__global__ void reduce_out_kernel(float* __restrict__ out){
    const int tid = threadIdx.x;
    if (tid >= B_ * NCLS) return;
    const int b = tid / NCLS;
    const int n = tid % NCLS;
    float s = 0.f;
    #pragma unroll 8
    for (int blk = 0; blk < RB; blk++){
        int b0 = (blk * RT) / HW;
        float v0 = g_part[(n * RB + blk) * 2 + 0];
        float v1 = g_part[(n * RB + blk) * 2 + 1];
        if (b0 == b)     s += v0;
        if (b0 + 1 == b) s += v1;
    }
    out[tid] = s;
}

extern "C" void kernel_launch(void* const* d_in, const int* in_sizes, int n_in,
                              void* d_out, int out_size){
    const float* x1 = (const float*)d_in[0];   // [16,64,21,21] fp32
    const float* x2 = (const float*)d_in[1];   // [10,64,2205]  fp32
    float* out = (float*)d_out;                // [16,10] fp32

    cudaFuncSetAttribute(sim_mma_kernel,
                         cudaFuncAttributeMaxDynamicSharedMemorySize, SMEM_REQ);
    norm_kernel<<<NU / 32, 256>>>(x1, x2);
    sim_mma_kernel<<<dim3(RB, NCLS), 256, SMEM_REQ>>>();
    reduce_out_kernel<<<1, 192>>>(out);
}